// round 13
// baseline (speedup 1.0000x reference)
#include <cuda_runtime.h>
#include <cuda_fp16.h>
#include <cstdint>

// ---------------------------------------------------------------------------
// Winograd F(2x2,3x3), fp16 split-precision GEMM via mma.sync (HMMA).
//   V_hi/V_lo[xy][t][c]  fp16, c fastest (128B rows)
//   U_hi[xy][k][c]       fp16 (U_lo dropped: weights' fp16 residual ~2^-11)
//   Per xy: M[t][k] = sum_c (V_hi+V_lo)[t][c]*U_hi[k][c]   (2 MMA passes)
//   Output transform A^T M A folded in registers (compile-time coeffs).
//   GEMM tile 64t x 64k -> ~115 regs -> 2 CTAs/SM for latency hiding.
// ---------------------------------------------------------------------------

#define TTOT 32768          // 8 * 64 * 64 tiles
#define CC 64
#define KK 64

__device__ __half g_Vhi[(size_t)16 * TTOT * CC];
__device__ __half g_Vlo[(size_t)16 * TTOT * CC];
__device__ __half g_Uhi[16 * KK * CC];

// ------------------------------- helpers -----------------------------------
__device__ __forceinline__ uint32_t smem_u32(const void* p) {
    uint32_t a;
    asm("{ .reg .u64 t; cvta.to.shared.u64 t, %1; cvt.u32.u64 %0, t; }"
        : "=r"(a) : "l"(p));
    return a;
}
__device__ __forceinline__ void cpasync16(uint32_t s, const void* g) {
    asm volatile("cp.async.cg.shared.global [%0], [%1], 16;" :: "r"(s), "l"(g));
}
__device__ __forceinline__ void ldm4(uint32_t* r, uint32_t addr) {
    asm volatile("ldmatrix.sync.aligned.m8n8.x4.shared.b16 {%0,%1,%2,%3}, [%4];"
                 : "=r"(r[0]), "=r"(r[1]), "=r"(r[2]), "=r"(r[3]) : "r"(addr));
}
__device__ __forceinline__ void mma16816(float* d, const uint32_t* a,
                                         const uint32_t* b) {
    asm volatile(
        "mma.sync.aligned.m16n8k16.row.col.f32.f16.f16.f32 "
        "{%0,%1,%2,%3}, {%4,%5,%6,%7}, {%8,%9}, {%0,%1,%2,%3};"
        : "+f"(d[0]), "+f"(d[1]), "+f"(d[2]), "+f"(d[3])
        : "r"(a[0]), "r"(a[1]), "r"(a[2]), "r"(a[3]), "r"(b[0]), "r"(b[1]));
}
__device__ __forceinline__ void split2(float a, float b, uint32_t& h, uint32_t& l) {
    __half ha = __float2half(a);
    __half hb = __float2half(b);
    __half la = __float2half(a - __half2float(ha));
    __half lb = __float2half(b - __half2float(hb));
    __half2 hv; hv.x = ha; hv.y = hb;
    __half2 lv; lv.x = la; lv.y = lb;
    h = *(uint32_t*)&hv;
    l = *(uint32_t*)&lv;
}

// --------------- kernel 1: input transform (+weight tail blocks) -----------
__global__ __launch_bounds__(256, 2) void k_transforms(const float* __restrict__ x,
                                                       const float* __restrict__ w)
{
    const int blk = blockIdx.x;

    if (blk >= 2048) {                       // ---- weight transform tail ----
        int g = (blk - 2048) * 256 + threadIdx.x;    // 4096
        int c = g & 63;
        int k = g >> 6;
        const float* wp = w + (k * CC + c) * 9;

        float gm[3][3];
#pragma unroll
        for (int i = 0; i < 3; ++i)
#pragma unroll
            for (int j = 0; j < 3; ++j) gm[i][j] = wp[i * 3 + j];

        float u[4][3];
#pragma unroll
        for (int j = 0; j < 3; ++j) {
            u[0][j] = gm[0][j];
            u[1][j] = 0.5f * (gm[0][j] + gm[1][j] + gm[2][j]);
            u[2][j] = 0.5f * (gm[0][j] - gm[1][j] + gm[2][j]);
            u[3][j] = gm[2][j];
        }
#pragma unroll
        for (int xx = 0; xx < 4; ++xx) {
            float v[4];
            v[0] = u[xx][0];
            v[1] = 0.5f * (u[xx][0] + u[xx][1] + u[xx][2]);
            v[2] = 0.5f * (u[xx][0] - u[xx][1] + u[xx][2]);
            v[3] = u[xx][2];
#pragma unroll
            for (int y = 0; y < 4; ++y)
                g_Uhi[(((xx * 4 + y) * KK + k) << 6) + c] = __float2half(v[y]);
        }
        return;
    }

    // ------------------------- input transform -----------------------------
    const int s  = blk & 3;
    const int bn = blk >> 2;
    const int b = bn >> 6, n = bn & 63;

    const int m = threadIdx.x >> 2;
    const int q = threadIdx.x & 3;
    const int t = bn * 64 + m;

    float wr[4][4][4];            // [r][xr][j]
#pragma unroll
    for (int r = 0; r < 4; ++r) {
        const int c = s * 16 + q * 4 + r;
        const float* p = x + ((size_t)(b * 64 + c) * 130 + 2 * n) * 130 + 2 * m;
        float d[4][4];
#pragma unroll
        for (int i = 0; i < 4; ++i) {
            float2 e0 = *(const float2*)(p + i * 130);
            float2 e1 = *(const float2*)(p + i * 130 + 2);
            d[i][0] = e0.x; d[i][1] = e0.y; d[i][2] = e1.x; d[i][3] = e1.y;
        }
#pragma unroll
        for (int j = 0; j < 4; ++j) {
            wr[r][0][j] = d[0][j] - d[2][j];
            wr[r][1][j] = d[1][j] + d[2][j];
            wr[r][2][j] = d[2][j] - d[1][j];
            wr[r][3][j] = d[1][j] - d[3][j];
        }
    }

#pragma unroll
    for (int xy = 0; xy < 16; ++xy) {
        const int xr = xy >> 2, yr = xy & 3;
        float v[4];
#pragma unroll
        for (int r = 0; r < 4; ++r) {
            const float* w4 = wr[r][xr];
            v[r] = (yr == 0) ? (w4[0] - w4[2])
                 : (yr == 1) ? (w4[1] + w4[2])
                 : (yr == 2) ? (w4[2] - w4[1])
                 :             (w4[1] - w4[3]);
        }
        uint32_t h0, l0, h1, l1;
        split2(v[0], v[1], h0, l0);
        split2(v[2], v[3], h1, l1);
        size_t base = (((size_t)xy * TTOT + t) << 6) + (s << 4) + (q << 2);
        *(uint2*)(g_Vhi + base) = make_uint2(h0, h1);
        *(uint2*)(g_Vlo + base) = make_uint2(l0, l1);
    }
}

// --------------- kernel 2: HMMA GEMM + fused output transform --------------
// CTA: 64 t (M) x 64 k (N) x 64 c (K). 8 warps as 4(M) x 2(N), warp 16x32.
// smem rows padded to 144B. 3-stage cp.async pipeline, 2 CTAs/SM.
#define SROW   144
#define VHI_O  0
#define VLO_O  9216           // 64*144
#define UHI_O  18432
#define BUFSZ  27648          // + 64*144
#define NSTAGE 3
#define SMEMSZ (NSTAGE * BUFSZ)

__device__ __forceinline__ void load_tiles(uint32_t sbase, int xy, int buf, int t0)
{
    const int tid = threadIdx.x;
    uint32_t sb = sbase + buf * BUFSZ;
    const char* gVh = (const char*)g_Vhi + (((size_t)xy * TTOT + t0) << 7);
    const char* gVl = (const char*)g_Vlo + (((size_t)xy * TTOT + t0) << 7);
    const char* gUh = (const char*)g_Uhi + ((size_t)xy << 13);
#pragma unroll
    for (int i = 0; i < 2; ++i) {           // V: 512 chunks of 16B each array
        int task = tid + i * 256;
        int row = task >> 3, ch = task & 7;
        cpasync16(sb + VHI_O + row * SROW + ch * 16, gVh + row * 128 + ch * 16);
        cpasync16(sb + VLO_O + row * SROW + ch * 16, gVl + row * 128 + ch * 16);
    }
#pragma unroll
    for (int i = 0; i < 2; ++i) {           // U hi: 512 chunks
        int task = tid + i * 256;
        int row = task >> 3, ch = task & 7;
        cpasync16(sb + UHI_O + row * SROW + ch * 16, gUh + row * 128 + ch * 16);
    }
    asm volatile("cp.async.commit_group;" ::: "memory");
}

__global__ __launch_bounds__(256, 2) void k_gemm_out(const float* __restrict__ bias,
                                                     float* __restrict__ out)
{
    extern __shared__ char smraw[];
    const uint32_t sbase = smem_u32(smraw);

    const int tid  = threadIdx.x;
    const int wid  = tid >> 5;
    const int lane = tid & 31;
    const int t0   = (511 - blockIdx.x) << 6;   // reverse order for L2 reuse
    const int m0   = (wid >> 1) << 4;       // warp row: 0,16,32,48
    const int n0   = (wid & 1) << 5;        // warp col: 0,32

    const int mat  = lane >> 3, lrow = lane & 7;
    const int aRow = ((mat & 1) << 3) + lrow;
    const int aCol = (mat >> 1) << 4;
    const int bRow = ((mat >> 1) << 3) + lrow;
    const int bCol = (mat & 1) << 4;

    load_tiles(sbase, 0, 0, t0);
    load_tiles(sbase, 1, 1, t0);
    load_tiles(sbase, 2, 2, t0);

    float y00[16], y01[16], y10[16], y11[16];
#pragma unroll
    for (int j = 0; j < 16; ++j) { y00[j] = 0.f; y01[j] = 0.f; y10[j] = 0.f; y11[j] = 0.f; }

#pragma unroll
    for (int xy = 0; xy < 16; ++xy) {
        if (xy <= 13)      asm volatile("cp.async.wait_group 2;" ::: "memory");
        else if (xy == 14) asm volatile("cp.async.wait_group 1;" ::: "memory");
        else               asm volatile("cp.async.wait_group 0;" ::: "memory");
        __syncthreads();

        const int buf = xy % NSTAGE;
        const uint32_t sb = sbase + buf * BUFSZ;
        float macc[4][4];
#pragma unroll
        for (int b = 0; b < 4; ++b)
#pragma unroll
            for (int c = 0; c < 4; ++c) macc[b][c] = 0.f;

#pragma unroll
        for (int kk = 0; kk < 4; ++kk) {
            uint32_t ah[4], al[4], bh[2][4];
            {
                uint32_t ra = (m0 + aRow) * SROW + (kk << 5) + aCol;
                ldm4(ah, sb + VHI_O + ra);
                ldm4(al, sb + VLO_O + ra);
            }
#pragma unroll
            for (int g = 0; g < 2; ++g) {
                uint32_t rb = (n0 + (g << 4) + bRow) * SROW + (kk << 5) + bCol;
                ldm4(bh[g], sb + UHI_O + rb);
            }
            // two passes over 4 independent accumulators: hh, lh
#pragma unroll
            for (int nt = 0; nt < 4; ++nt)
                mma16816(macc[nt], ah, &bh[nt >> 1][(nt & 1) << 1]);
#pragma unroll
            for (int nt = 0; nt < 4; ++nt)
                mma16816(macc[nt], al, &bh[nt >> 1][(nt & 1) << 1]);
        }
        __syncthreads();
        if (xy + NSTAGE < 16) load_tiles(sbase, xy + NSTAGE, buf, t0);

        const int xx = xy >> 2, yy = xy & 3;
        const float a0x = (xx == 3) ? 0.f : 1.f;
        const float a1x = (xx == 0) ? 0.f : ((xx == 1) ? 1.f : -1.f);
        const float a0y = (yy == 3) ? 0.f : 1.f;
        const float a1y = (yy == 0) ? 0.f : ((yy == 1) ? 1.f : -1.f);
        const float c00 = a0x * a0y, c01 = a0x * a1y;
        const float c10 = a1x * a0y, c11 = a1x * a1y;
#pragma unroll
        for (int nt = 0; nt < 4; ++nt)
#pragma unroll
            for (int r = 0; r < 4; ++r) {
                int e = (nt << 2) + r;
                float v = macc[nt][r];
                if (c00 != 0.f) y00[e] += c00 * v;
                if (c01 != 0.f) y01[e] += c01 * v;
                if (c10 != 0.f) y10[e] += c10 * v;
                if (c11 != 0.f) y11[e] += c11 * v;
            }
    }

    // epilogue: each y element is one (t,k) -> 2x2 output pixels
    {
        int tb = t0 + m0 + (lane >> 2);
#pragma unroll
        for (int nt = 0; nt < 4; ++nt) {
            int k0 = n0 + (nt << 3) + ((lane & 3) << 1);
            float bv0 = __ldg(&bias[k0]);
            float bv1 = __ldg(&bias[k0 + 1]);
#pragma unroll
            for (int rr = 0; rr < 2; ++rr) {
                int t = tb + (rr << 3);
                int b = t >> 12, n = (t >> 6) & 63, m = t & 63;
                float* o0 = out + (((size_t)(b * KK + k0) * 128 + 2 * n) * 128 + 2 * m);
                float* o1 = o0 + 128 * 128;
                int e = (nt << 2) + (rr << 1);
                *(float2*)o0         = make_float2(y00[e] + bv0,     y01[e] + bv0);
                *(float2*)(o0 + 128) = make_float2(y10[e] + bv0,     y11[e] + bv0);
                *(float2*)o1         = make_float2(y00[e + 1] + bv1, y01[e + 1] + bv1);
                *(float2*)(o1 + 128) = make_float2(y10[e + 1] + bv1, y11[e + 1] + bv1);
            }
        }
    }
}

// ---------------------------------------------------------------------------
extern "C" void kernel_launch(void* const* d_in, const int* in_sizes, int n_in,
                              void* d_out, int out_size)
{
    const float* x    = (const float*)d_in[0];
    const float* w    = (const float*)d_in[1];
    const float* bias = (const float*)d_in[2];
    float* out        = (float*)d_out;

    cudaFuncSetAttribute(k_gemm_out,
                         cudaFuncAttributeMaxDynamicSharedMemorySize, SMEMSZ);

    k_transforms<<<2064, 256>>>(x, w);
    k_gemm_out<<<512, 256, SMEMSZ>>>(bias, out);
}

// round 14
// speedup vs baseline: 1.0531x; 1.0531x over previous
#include <cuda_runtime.h>
#include <cuda_fp16.h>
#include <cstdint>

// ---------------------------------------------------------------------------
// Winograd F(2x2,3x3), FUSED: input transform + fp16 split GEMM + output
// transform in ONE kernel. V never touches DRAM.
//   CTA = one bn (64 tiles t, all 64 c, all 64 k). Per xy:
//     V tile (64t x 64c, fp16 hi+lo) computed from smem-staged x into a
//     double-buffered smem tile, then HMMA GEMM vs U_hi (cp.async from L2),
//     A^T M A folded into y-registers with compile-time coeffs.
//   product = (V_hi + V_lo) * U_hi   (U residual ~2^-11 dropped)
// ---------------------------------------------------------------------------

#define CC 64
#define KK 64

__device__ __half g_Uhi[16 * KK * CC];

// ------------------------------- helpers -----------------------------------
__device__ __forceinline__ uint32_t smem_u32(const void* p) {
    uint32_t a;
    asm("{ .reg .u64 t; cvta.to.shared.u64 t, %1; cvt.u32.u64 %0, t; }"
        : "=r"(a) : "l"(p));
    return a;
}
__device__ __forceinline__ void cpasync16(uint32_t s, const void* g) {
    asm volatile("cp.async.cg.shared.global [%0], [%1], 16;" :: "r"(s), "l"(g));
}
__device__ __forceinline__ void ldm4(uint32_t* r, uint32_t addr) {
    asm volatile("ldmatrix.sync.aligned.m8n8.x4.shared.b16 {%0,%1,%2,%3}, [%4];"
                 : "=r"(r[0]), "=r"(r[1]), "=r"(r[2]), "=r"(r[3]) : "r"(addr));
}
__device__ __forceinline__ void mma16816(float* d, const uint32_t* a,
                                         const uint32_t* b) {
    asm volatile(
        "mma.sync.aligned.m16n8k16.row.col.f32.f16.f16.f32 "
        "{%0,%1,%2,%3}, {%4,%5,%6,%7}, {%8,%9}, {%0,%1,%2,%3};"
        : "+f"(d[0]), "+f"(d[1]), "+f"(d[2]), "+f"(d[3])
        : "r"(a[0]), "r"(a[1]), "r"(a[2]), "r"(a[3]), "r"(b[0]), "r"(b[1]));
}
__device__ __forceinline__ void split2(float a, float b, uint32_t& h, uint32_t& l) {
    __half ha = __float2half(a);
    __half hb = __float2half(b);
    __half la = __float2half(a - __half2float(ha));
    __half lb = __float2half(b - __half2float(hb));
    __half2 hv; hv.x = ha; hv.y = hb;
    __half2 lv; lv.x = la; lv.y = lb;
    h = *(uint32_t*)&hv;
    l = *(uint32_t*)&lv;
}

// ------------------------- kernel 1: weight transform ----------------------
__global__ void k_weight_transform(const float* __restrict__ w)
{
    int g = blockIdx.x * blockDim.x + threadIdx.x;   // 4096
    if (g >= KK * CC) return;
    int c = g & 63;
    int k = g >> 6;
    const float* wp = w + (k * CC + c) * 9;

    float gm[3][3];
#pragma unroll
    for (int i = 0; i < 3; ++i)
#pragma unroll
        for (int j = 0; j < 3; ++j) gm[i][j] = wp[i * 3 + j];

    float u[4][3];
#pragma unroll
    for (int j = 0; j < 3; ++j) {
        u[0][j] = gm[0][j];
        u[1][j] = 0.5f * (gm[0][j] + gm[1][j] + gm[2][j]);
        u[2][j] = 0.5f * (gm[0][j] - gm[1][j] + gm[2][j]);
        u[3][j] = gm[2][j];
    }
#pragma unroll
    for (int xx = 0; xx < 4; ++xx) {
        float v[4];
        v[0] = u[xx][0];
        v[1] = 0.5f * (u[xx][0] + u[xx][1] + u[xx][2]);
        v[2] = 0.5f * (u[xx][0] - u[xx][1] + u[xx][2]);
        v[3] = u[xx][2];
#pragma unroll
        for (int y = 0; y < 4; ++y)
            g_Uhi[(((xx * 4 + y) * KK + k) << 6) + c] = __float2half(v[y]);
    }
}

// --------------------------- kernel 2: fused -------------------------------
// smem: xs fp32 slab (64c x [4 rows x 132 + pad] = 534 words/c) |
//       V bufs 2 x (hi 64x144 + lo 64x144) | U bufs 2 x 64x144
#define RSTRW  132
#define CSTRW  534            // %8 == 6 -> <=2-way LDS bank conflicts
#define XS_BYTES (64 * CSTRW * 4)           // 136704
#define SROW   144
#define VB_OFF  XS_BYTES
#define VBUF_SZ 18432                       // hi 9216 + lo 9216
#define UB_OFF  (VB_OFF + 2 * VBUF_SZ)      // 173568
#define UBUF_SZ 9216
#define SMEMSZ  (UB_OFF + 2 * UBUF_SZ)      // 192000

__global__ __launch_bounds__(256, 1) void k_fused(const float* __restrict__ x,
                                                  const float* __restrict__ bias,
                                                  float* __restrict__ out)
{
    extern __shared__ char smraw[];
    const uint32_t sbase = smem_u32(smraw);
    float* xsf = (float*)smraw;

    const int tid  = threadIdx.x;
    const int wid  = tid >> 5;
    const int lane = tid & 31;
    const int bn = blockIdx.x;
    const int b = bn >> 6, n = bn & 63;

    // GEMM geometry (64t x 64k, 8 warps as 4(M) x 2(N), warp 16x32)
    const int m0 = (wid >> 1) << 4;
    const int n0 = (wid & 1) << 5;
    const int mat = lane >> 3, lrow = lane & 7;
    const int aRow = ((mat & 1) << 3) + lrow;
    const int aCol = (mat >> 1) << 4;
    const int bRow = ((mat >> 1) << 3) + lrow;
    const int bCol = (mat & 1) << 4;

    // transform geometry: thread = (m, q); handles c = 16s + 4q + r
    const int tm = tid >> 2;
    const int tq = tid & 3;

    // prefetch U(0) while staging x
    {
        const char* gU = (const char*)g_Uhi;
#pragma unroll
        for (int i = 0; i < 2; ++i) {
            int task = tid + i * 256;
            int row = task >> 3, ch = task & 7;
            cpasync16(sbase + UB_OFF + row * SROW + ch * 16, gU + row * 128 + ch * 16);
        }
        asm volatile("cp.async.commit_group;" ::: "memory");
    }

    // stage x slab: 64 c x 4 rows x 130 cols (float2 chunks)
    for (int i = tid; i < 64 * 260; i += 256) {
        int c = i / 260;
        int rem = i - c * 260;
        int row = rem / 65;
        int j = rem - row * 65;
        float2 v = *(const float2*)(x + ((size_t)(b * 64 + c) * 130 + 2 * n + row) * 130 + 2 * j);
        *(float2*)(xsf + c * CSTRW + row * RSTRW + 2 * j) = v;
    }
    __syncthreads();

    float y00[16], y01[16], y10[16], y11[16];
#pragma unroll
    for (int j = 0; j < 16; ++j) { y00[j] = 0.f; y01[j] = 0.f; y10[j] = 0.f; y11[j] = 0.f; }

    float Z[4][4][4];   // row-pass values: [s][r][j], c = 16s + 4q + r

#pragma unroll
    for (int xr = 0; xr < 4; ++xr) {
        // Z = dA (+/-) dB per xr:  xr0: d0-d2, xr1: d1+d2, xr2: d2-d1, xr3: d1-d3
        const int rA = (xr == 0) ? 0 : ((xr == 2) ? 2 : 1);
        const int rB = (xr == 0) ? 2 : ((xr == 1) ? 2 : ((xr == 2) ? 1 : 3));
        const bool addf = (xr == 1);
#pragma unroll
        for (int s = 0; s < 4; ++s)
#pragma unroll
            for (int r = 0; r < 4; ++r) {
                const int c = 16 * s + 4 * tq + r;
                const float* pa = xsf + c * CSTRW + rA * RSTRW + 2 * tm;
                const float* pb = xsf + c * CSTRW + rB * RSTRW + 2 * tm;
                float2 a0 = *(const float2*)pa;
                float2 a1 = *(const float2*)(pa + 2);
                float2 b0 = *(const float2*)pb;
                float2 b1 = *(const float2*)(pb + 2);
                if (addf) {
                    Z[s][r][0] = a0.x + b0.x; Z[s][r][1] = a0.y + b0.y;
                    Z[s][r][2] = a1.x + b1.x; Z[s][r][3] = a1.y + b1.y;
                } else {
                    Z[s][r][0] = a0.x - b0.x; Z[s][r][1] = a0.y - b0.y;
                    Z[s][r][2] = a1.x - b1.x; Z[s][r][3] = a1.y - b1.y;
                }
            }

#pragma unroll
        for (int yr = 0; yr < 4; ++yr) {
            const int xy = xr * 4 + yr;
            const int p = xy & 1;

            // ---- build V tile (hi/lo) into buffer p ----
#pragma unroll
            for (int s = 0; s < 4; ++s) {
                float v_[4];
#pragma unroll
                for (int r = 0; r < 4; ++r)
                    v_[r] = (yr == 0) ? (Z[s][r][0] - Z[s][r][2])
                          : (yr == 1) ? (Z[s][r][1] + Z[s][r][2])
                          : (yr == 2) ? (Z[s][r][2] - Z[s][r][1])
                          :             (Z[s][r][1] - Z[s][r][3]);
                uint32_t h0, l0, h1, l1;
                split2(v_[0], v_[1], h0, l0);
                split2(v_[2], v_[3], h1, l1);
                const int off = tm * SROW + s * 32 + tq * 8;
                *(uint2*)(smraw + VB_OFF + p * VBUF_SZ + off)        = make_uint2(h0, h1);
                *(uint2*)(smraw + VB_OFF + p * VBUF_SZ + 9216 + off) = make_uint2(l0, l1);
            }
            __syncthreads();   // V(p) visible; all warps past ldmatrix of xy-1

            // ---- prefetch U(xy+1) into the buffer freed at xy-1 ----
            if (xy + 1 < 16) {
                const char* gU = (const char*)g_Uhi + ((size_t)(xy + 1) << 13);
                const uint32_t ub = sbase + UB_OFF + ((xy + 1) & 1) * UBUF_SZ;
#pragma unroll
                for (int i = 0; i < 2; ++i) {
                    int task = tid + i * 256;
                    int row = task >> 3, ch = task & 7;
                    cpasync16(ub + row * SROW + ch * 16, gU + row * 128 + ch * 16);
                }
                asm volatile("cp.async.commit_group;" ::: "memory");
                asm volatile("cp.async.wait_group 1;" ::: "memory");   // U(xy) ready
            } else {
                asm volatile("cp.async.wait_group 0;" ::: "memory");
            }

            // ---- GEMM this xy ----
            const uint32_t vb = sbase + VB_OFF + p * VBUF_SZ;
            const uint32_t ub = sbase + UB_OFF + (xy & 1) * UBUF_SZ;
            float macc[4][4];
#pragma unroll
            for (int bq = 0; bq < 4; ++bq)
#pragma unroll
                for (int cq = 0; cq < 4; ++cq) macc[bq][cq] = 0.f;

#pragma unroll
            for (int kk = 0; kk < 4; ++kk) {
                uint32_t ah[4], al[4], bh[2][4];
                const uint32_t ra = (m0 + aRow) * SROW + (kk << 5) + aCol;
                ldm4(ah, vb + ra);
                ldm4(al, vb + 9216 + ra);
#pragma unroll
                for (int g = 0; g < 2; ++g) {
                    const uint32_t rb = (n0 + (g << 4) + bRow) * SROW + (kk << 5) + bCol;
                    ldm4(bh[g], ub + rb);
                }
#pragma unroll
                for (int nt = 0; nt < 4; ++nt)
                    mma16816(macc[nt], ah, &bh[nt >> 1][(nt & 1) << 1]);
#pragma unroll
                for (int nt = 0; nt < 4; ++nt)
                    mma16816(macc[nt], al, &bh[nt >> 1][(nt & 1) << 1]);
            }

            // ---- fold output transform (compile-time coeffs) ----
            const float a0x = (xr == 3) ? 0.f : 1.f;
            const float a1x = (xr == 0) ? 0.f : ((xr == 1) ? 1.f : -1.f);
            const float a0y = (yr == 3) ? 0.f : 1.f;
            const float a1y = (yr == 0) ? 0.f : ((yr == 1) ? 1.f : -1.f);
            const float c00 = a0x * a0y, c01 = a0x * a1y;
            const float c10 = a1x * a0y, c11 = a1x * a1y;
#pragma unroll
            for (int nt = 0; nt < 4; ++nt)
#pragma unroll
                for (int r = 0; r < 4; ++r) {
                    const int e = (nt << 2) + r;
                    const float v = macc[nt][r];
                    if (c00 != 0.f) y00[e] += c00 * v;
                    if (c01 != 0.f) y01[e] += c01 * v;
                    if (c10 != 0.f) y10[e] += c10 * v;
                    if (c11 != 0.f) y11[e] += c11 * v;
                }
        }
    }

    // ---- epilogue: each y element is one (t,k) -> 2x2 output pixels ----
    {
        const int t0 = bn << 6;
        const int tb = t0 + m0 + (lane >> 2);
#pragma unroll
        for (int nt = 0; nt < 4; ++nt) {
            const int k0 = n0 + (nt << 3) + ((lane & 3) << 1);
            const float bv0 = __ldg(&bias[k0]);
            const float bv1 = __ldg(&bias[k0 + 1]);
#pragma unroll
            for (int rr = 0; rr < 2; ++rr) {
                const int t = tb + (rr << 3);
                const int bb = t >> 12, nn = (t >> 6) & 63, mm = t & 63;
                float* o0 = out + (((size_t)(bb * KK + k0) * 128 + 2 * nn) * 128 + 2 * mm);
                float* o1 = o0 + 128 * 128;
                const int e = (nt << 2) + (rr << 1);
                *(float2*)o0         = make_float2(y00[e] + bv0,     y01[e] + bv0);
                *(float2*)(o0 + 128) = make_float2(y10[e] + bv0,     y11[e] + bv0);
                *(float2*)o1         = make_float2(y00[e + 1] + bv1, y01[e + 1] + bv1);
                *(float2*)(o1 + 128) = make_float2(y10[e + 1] + bv1, y11[e + 1] + bv1);
            }
        }
    }
}

// ---------------------------------------------------------------------------
extern "C" void kernel_launch(void* const* d_in, const int* in_sizes, int n_in,
                              void* d_out, int out_size)
{
    const float* x    = (const float*)d_in[0];
    const float* w    = (const float*)d_in[1];
    const float* bias = (const float*)d_in[2];
    float* out        = (float*)d_out;

    cudaFuncSetAttribute(k_fused,
                         cudaFuncAttributeMaxDynamicSharedMemorySize, SMEMSZ);

    k_weight_transform<<<16, 256>>>(w);
    k_fused<<<512, 256, SMEMSZ>>>(x, bias, out);
}